// round 15
// baseline (speedup 1.0000x reference)
#include <cuda_runtime.h>
#include <cuda_bf16.h>
#include <math.h>
#include <stdint.h>

typedef unsigned long long u64;

#define NPIX  65536   // 256*256
#define BATCH 4

// ---------------- scratch (device globals: allocation is forbidden) -----------
__device__ float g_t[(size_t)BATCH * 256 * NPIX];     // 256 MB : t = w_in @ x
__device__ float g_qv[(size_t)BATCH * 128 * NPIX];    // 128 MB : q, v
__device__ __nv_bfloat16 g_a2[256 * 192];             // bf16-split w_in, [o][192]
__device__ __nv_bfloat16 g_M2[BATCH * 64 * 192];      // bf16-split M = w_out@attn
__device__ float g_sumsq[BATCH * 128];
__device__ float g_gram[BATCH * 64 * 64];

// ---------------- helpers -----------------------------------------------------
__device__ __forceinline__ u64 pack2(float x, float y) {
    u64 d;
    asm("mov.b64 %0, {%1, %2};" : "=l"(d) : "f"(x), "f"(y));
    return d;
}
__device__ __forceinline__ uint32_t smem_to_u32(const void* p) {
    uint32_t a;
    asm("{ .reg .u64 t; cvta.to.shared.u64 t, %1; cvt.u32.u64 %0, t; }" : "=r"(a) : "l"(p));
    return a;
}
__device__ __forceinline__ void ldsm_x4(uint32_t& r0, uint32_t& r1, uint32_t& r2, uint32_t& r3,
                                        uint32_t addr) {
    asm volatile("ldmatrix.sync.aligned.m8n8.x4.shared.b16 {%0,%1,%2,%3}, [%4];"
        : "=r"(r0), "=r"(r1), "=r"(r2), "=r"(r3) : "r"(addr));
}
__device__ __forceinline__ void mma_bf16(float* d, const uint32_t* a, const uint32_t* b) {
    asm volatile("mma.sync.aligned.m16n8k16.row.col.f32.bf16.bf16.f32 "
        "{%0,%1,%2,%3}, {%4,%5,%6,%7}, {%8,%9}, {%0,%1,%2,%3};"
        : "+f"(d[0]), "+f"(d[1]), "+f"(d[2]), "+f"(d[3])
        : "r"(a[0]), "r"(a[1]), "r"(a[2]), "r"(a[3]), "r"(b[0]), "r"(b[1]));
}
__device__ __forceinline__ void cp16(uint32_t smem_addr, const void* gptr) {
    asm volatile("cp.async.cg.shared.global [%0], [%1], 16;" :: "r"(smem_addr), "l"(gptr));
}
#define CP_COMMIT() asm volatile("cp.async.commit_group;" ::: "memory")
#define CP_WAIT(n)  asm volatile("cp.async.wait_group %0;" :: "n"(n) : "memory")

__device__ __forceinline__ unsigned short bfbits(float v) {
    __nv_bfloat16 h = __float2bfloat16(v);
    return *(unsigned short*)&h;
}
__device__ __forceinline__ uint32_t bfpair(float a, float b) {
    return (uint32_t)bfbits(a) | ((uint32_t)bfbits(b) << 16);
}

// ---------------- weight split + zero stats (merged) --------------------------
__global__ void wsplit(const float* __restrict__ w_in) {
    const int gi = threadIdx.x + blockIdx.x * blockDim.x;
    const int gs = blockDim.x * gridDim.x;
    for (int i = gi; i < 256 * 192; i += gs) {
        int o = i / 192, k = i % 192;
        int c = k / 3, j = k % 3;
        float w = w_in[o * 64 + c];
        __nv_bfloat16 hi = __float2bfloat16(w);
        if (j == 2) g_a2[i] = __float2bfloat16(w - __bfloat162float(hi));
        else        g_a2[i] = hi;
    }
    for (int i = gi; i < BATCH * 128 + BATCH * 64 * 64; i += gs) {
        if (i < BATCH * 128) g_sumsq[i] = 0.f;
        else                 g_gram[i - BATCH * 128] = 0.f;
    }
}

// ---------------- tensor-core gemm1: half-A resident, 2 CTAs/SM ---------------
// CTA owns 128 of 256 outputs (A half = 50KB, staged once) and grid-strides
// over 64-px tiles. 8 warps = 4(m:32) x 2(n:32). X double-buffered.
// grid (37, 2, BATCH) = 296 CTAs = 2 full waves. smem 109KB -> 2 CTAs/SM.
#define GH_RB     400
#define GH_A_ARR  (128 * GH_RB)                // 51200
#define GH_B_ARR  (64 * GH_RB)                 // 25600
#define GH_X_RB   272
#define GH_X_ARR  (64 * GH_X_RB)               // 17408
#define GH_B_OFF  GH_A_ARR
#define GH_X_OFF  (GH_A_ARR + GH_B_ARR)
#define GH_SMEM   (GH_A_ARR + GH_B_ARR + 2 * GH_X_ARR)   // 111616
#define GH_NTILE  1024
#define GH_GRIDX  37
__global__ __launch_bounds__(256, 2) void gemm1_half(const float* __restrict__ x) {
    extern __shared__ char sm[];
    const int tid = threadIdx.x, wid = tid >> 5, lane = tid & 31;
    const int b = blockIdx.z;
    const int obase = blockIdx.y * 128;
    const int wm = wid & 3, wn = wid >> 2;

    const uint32_t smem_base = smem_to_u32(sm);
    const char*  Agl = (const char*)(g_a2 + (size_t)obase * 192);
    const float* xb  = x + (size_t)b * 64 * NPIX;

    // stage A half once: 128 rows x 24 slabs of 16B (12 per thread)
#pragma unroll
    for (int e = 0; e < 3072; e += 256) {
        int u = e + tid;
        int r = u / 24, sl = u % 24;
        cp16(smem_base + r * GH_RB + sl * 16, Agl + r * 384 + sl * 16);
    }

    auto prefetch_x = [&](int t, int s) {
        uint32_t xbs = smem_base + GH_X_OFF + s * GH_X_ARR;
        const float* src = xb + t * 64;
#pragma unroll
        for (int e = 0; e < 1024; e += 256) {
            int u = e + tid;
            int ch = u >> 4, sl = u & 15;
            cp16(xbs + ch * GH_X_RB + sl * 16, src + (size_t)ch * NPIX + sl * 4);
        }
    };

    const int lrow = lane & 15;
    const int lkh  = (lane >> 4) * 8;
    const int g = lane >> 2, T = lane & 3;
    const int cp_p = tid & 63;           // convert pixel
    const int cp_g0 = tid >> 6;          // convert channel-pair groups cp_g0, cp_g0+4

    int t = blockIdx.x;
    int s = 0;
    prefetch_x(t, 0);
    CP_COMMIT();

    while (t < GH_NTILE) {
        const int nt = t + GH_GRIDX;
        if (nt < GH_NTILE) { prefetch_x(nt, s ^ 1); CP_COMMIT(); CP_WAIT(1); }
        else               { CP_WAIT(0); }
        __syncthreads();

        // convert raw x[s] -> B (2 groups of 4 channel-pairs per thread)
        {
            const float* xs = (const float*)(sm + GH_X_OFF + s * GH_X_ARR);
#pragma unroll
            for (int gsel = 0; gsel < 2; ++gsel) {
                int cg = cp_g0 + gsel * 4;
                uint32_t* brow = (uint32_t*)(sm + GH_B_OFF + cp_p * GH_RB) + cg * 12;
                uint32_t w[12];
#pragma unroll
                for (int i = 0; i < 4; ++i) {
                    int cpi = cg * 4 + i;
                    float x0 = xs[(2 * cpi) * 68 + cp_p];
                    float x1 = xs[(2 * cpi + 1) * 68 + cp_p];
                    float h0 = __bfloat162float(__float2bfloat16(x0));
                    float h1 = __bfloat162float(__float2bfloat16(x1));
                    float l0 = x0 - h0, l1 = x1 - h1;
                    w[i * 3 + 0] = bfpair(h0, l0);
                    w[i * 3 + 1] = bfpair(h0, h1);
                    w[i * 3 + 2] = bfpair(l1, h1);
                }
#pragma unroll
                for (int i = 0; i < 3; ++i)
                    *(uint4*)(brow + i * 4) = make_uint4(w[i*4], w[i*4+1], w[i*4+2], w[i*4+3]);
            }
        }
        __syncthreads();

        float acc[2][4][4];
#pragma unroll
        for (int mi = 0; mi < 2; ++mi)
#pragma unroll
            for (int ni = 0; ni < 4; ++ni)
#pragma unroll
                for (int r = 0; r < 4; ++r) acc[mi][ni][r] = 0.f;

        uint32_t bb = smem_base + GH_B_OFF;
#pragma unroll
        for (int ks = 0; ks < 12; ++ks) {
            uint32_t a[2][4];
#pragma unroll
            for (int mi = 0; mi < 2; ++mi) {
                uint32_t addr = smem_base + (wm * 32 + mi * 16 + lrow) * GH_RB + ks * 32 + lkh * 2;
                ldsm_x4(a[mi][0], a[mi][1], a[mi][2], a[mi][3], addr);
            }
            uint32_t bf[4][2];
#pragma unroll
            for (int nq = 0; nq < 2; ++nq) {
                uint32_t r0, r1, r2, r3;
                uint32_t addr = bb + (wn * 32 + nq * 16 + lrow) * GH_RB + ks * 32 + lkh * 2;
                ldsm_x4(r0, r1, r2, r3, addr);
                bf[2 * nq][0] = r0;     bf[2 * nq][1] = r2;
                bf[2 * nq + 1][0] = r1; bf[2 * nq + 1][1] = r3;
            }
#pragma unroll
            for (int mi = 0; mi < 2; ++mi)
#pragma unroll
                for (int ni = 0; ni < 4; ++ni)
                    mma_bf16(acc[mi][ni], a[mi], bf[ni]);
        }
        __syncthreads();   // B reuse by next iteration's convert

        // epilogue
#pragma unroll
        for (int mi = 0; mi < 2; ++mi) {
            int m = obase + wm * 32 + mi * 16 + g;
            float* rowp = g_t + ((size_t)b * 256 + m) * NPIX + t * 64 + wn * 32 + T * 2;
#pragma unroll
            for (int ni = 0; ni < 4; ++ni) {
                *(u64*)(rowp + ni * 8) = pack2(acc[mi][ni][0], acc[mi][ni][1]);
                *(u64*)(rowp + ni * 8 + (size_t)8 * NPIX) = pack2(acc[mi][ni][2], acc[mi][ni][3]);
            }
        }
        t = nt;
        s ^= 1;
    }
}

// ---------------- depthwise 3x3 conv + gate, float4 (round-9 exact) ----------
__global__ __launch_bounds__(256) void conv_mul(const float* __restrict__ w_dw)
{
    __shared__ float st[34][264];
    const int tid = threadIdx.x;
    const int jj = blockIdx.y, b = blockIdx.z, r0 = blockIdx.x * 32;

    const float* t1 = g_t + ((size_t)b * 256 + jj) * NPIX;
    const float* t2 = g_t + ((size_t)b * 256 + 128 + jj) * NPIX;
    float* outp = g_qv + ((size_t)b * 128 + jj) * NPIX;

    float wd[9];
#pragma unroll
    for (int i = 0; i < 9; ++i) wd[i] = w_dw[jj * 9 + i];

#pragma unroll
    for (int e = 0; e < 2176; e += 256) {
        int u = e + tid;
        if (u < 2176) {
            int rr = u >> 6, q4 = u & 63;
            int row = r0 - 1 + rr;
            float4 v = make_float4(0.f, 0.f, 0.f, 0.f);
            if (row >= 0 && row < 256)
                v = *(const float4*)(t1 + row * 256 + q4 * 4);
            *(float4*)&st[rr][4 + q4 * 4] = v;
        }
    }
    if (tid < 34) { st[tid][3] = 0.f; st[tid][260] = 0.f; }
    __syncthreads();

    const int ty = tid >> 6, tc = tid & 63;
    const int c0 = tc * 4;
#pragma unroll
    for (int r = ty * 8; r < ty * 8 + 8; ++r) {
        float s0 = 0.f, s1 = 0.f, s2 = 0.f, s3 = 0.f;
#pragma unroll
        for (int ky = 0; ky < 3; ++ky) {
            const float* rowp = &st[r + ky][4 + c0];
            float4 m = *(const float4*)rowp;
            float left = rowp[-1], right = rowp[4];
            float w0 = wd[ky * 3 + 0], w1 = wd[ky * 3 + 1], w2 = wd[ky * 3 + 2];
            s0 += w0 * left + w1 * m.x + w2 * m.y;
            s1 += w0 * m.x  + w1 * m.y + w2 * m.z;
            s2 += w0 * m.y  + w1 * m.z + w2 * m.w;
            s3 += w0 * m.z  + w1 * m.w + w2 * right;
        }
        int p = (r0 + r) * 256 + c0;
        float4 g4 = *(const float4*)(t2 + p);
        float4 o = make_float4(s0 * g4.x, s1 * g4.y, s2 * g4.z, s3 * g4.w);
        *(float4*)(outp + p) = o;
    }
}

// ---------------- tensor-core gram + sumsq (round-14 exact) -------------------
#define GR_RB     208
#define GR_XRB    144
#define GR_A_OFF  0
#define GR_B_OFF  13312
#define GR_Q_OFF  26624
#define GR_V_OFF  35840
#define GR_STAGE  45056
#define GR_SMEM   (2 * GR_STAGE)
#define GR_NCHUNK 2048
__global__ __launch_bounds__(256, 2) void gram_mma()
{
    extern __shared__ char sm[];
    const int tid = threadIdx.x, wid = tid >> 5, lane = tid & 31;
    const int b = blockIdx.y;
    const int wk = wid >> 2;
    const int warpM = wid & 1, warpN = (wid >> 1) & 1;

    const uint32_t smem_base = smem_to_u32(sm);
    const float* qsrc = g_qv + (size_t)b * 128 * NPIX;
    const float* vsrc = qsrc + (size_t)64 * NPIX;

    auto prefetch = [&](int ci, int s) {
        int pbase = ci * 32;
        uint32_t qb = smem_base + s * GR_STAGE + GR_Q_OFF;
        uint32_t vb = smem_base + s * GR_STAGE + GR_V_OFF;
#pragma unroll
        for (int e = 0; e < 512; e += 256) {
            int u = e + tid;
            int ch = u >> 3, sl = u & 7;
            cp16(qb + ch * GR_XRB + sl * 16, qsrc + (size_t)ch * NPIX + pbase + sl * 4);
        }
#pragma unroll
        for (int e = 0; e < 512; e += 256) {
            int u = e + tid;
            int ch = u >> 3, sl = u & 7;
            cp16(vb + ch * GR_XRB + sl * 16, vsrc + (size_t)ch * NPIX + pbase + sl * 4);
        }
    };

    const int lrow = lane & 15;
    const int lkh  = (lane >> 4) * 8;

    float acc[2][4][4];
#pragma unroll
    for (int mi = 0; mi < 2; ++mi)
#pragma unroll
        for (int ni = 0; ni < 4; ++ni)
#pragma unroll
            for (int r = 0; r < 4; ++r) acc[mi][ni][r] = 0.f;
    float ssq = 0.f, ssv = 0.f;

    const int cch = tid >> 2;
    const int ppr = (tid & 3) * 4;

    int ci = blockIdx.x;
    int s = 0;
    prefetch(ci, 0);
    CP_COMMIT();

    while (ci < GR_NCHUNK) {
        const int nci = ci + gridDim.x;
        const bool more = nci < GR_NCHUNK;
        if (more) { prefetch(nci, s ^ 1); CP_COMMIT(); CP_WAIT(1); }
        else      { CP_WAIT(0); }
        __syncthreads();

        {
            const float* rq = (const float*)(sm + s * GR_STAGE + GR_Q_OFF) + cch * 36 + ppr * 2;
            const float* rv = (const float*)(sm + s * GR_STAGE + GR_V_OFF) + cch * 36 + ppr * 2;
            float4 qa = *(const float4*)rq, qb4 = *(const float4*)(rq + 4);
            float4 va = *(const float4*)rv, vb4 = *(const float4*)(rv + 4);
            float qq[8] = {qa.x, qa.y, qa.z, qa.w, qb4.x, qb4.y, qb4.z, qb4.w};
            float vv[8] = {va.x, va.y, va.z, va.w, vb4.x, vb4.y, vb4.z, vb4.w};
            uint32_t wq[12], wv[12];
#pragma unroll
            for (int pr = 0; pr < 4; ++pr) {
                float q0 = qq[2 * pr], q1 = qq[2 * pr + 1];
                float v0 = vv[2 * pr], v1 = vv[2 * pr + 1];
                ssq += q0 * q0 + q1 * q1;
                ssv += v0 * v0 + v1 * v1;
                float qh0 = __bfloat162float(__float2bfloat16(q0));
                float qh1 = __bfloat162float(__float2bfloat16(q1));
                float vh0 = __bfloat162float(__float2bfloat16(v0));
                float vh1 = __bfloat162float(__float2bfloat16(v1));
                float ql0 = q0 - qh0, ql1 = q1 - qh1;
                float vl0 = v0 - vh0, vl1 = v1 - vh1;
                wq[pr * 3 + 0] = bfpair(qh0, qh0);
                wq[pr * 3 + 1] = bfpair(ql0, qh1);
                wq[pr * 3 + 2] = bfpair(qh1, ql1);
                wv[pr * 3 + 0] = bfpair(vh0, vl0);
                wv[pr * 3 + 1] = bfpair(vh0, vh1);
                wv[pr * 3 + 2] = bfpair(vl1, vh1);
            }
            uint32_t* aq = (uint32_t*)(sm + s * GR_STAGE + GR_A_OFF + cch * GR_RB) + ppr * 3;
            uint32_t* bv = (uint32_t*)(sm + s * GR_STAGE + GR_B_OFF + cch * GR_RB) + ppr * 3;
#pragma unroll
            for (int i = 0; i < 3; ++i) {
                *(uint4*)(aq + i * 4) = make_uint4(wq[i*4], wq[i*4+1], wq[i*4+2], wq[i*4+3]);
                *(uint4*)(bv + i * 4) = make_uint4(wv[i*4], wv[i*4+1], wv[i*4+2], wv[i*4+3]);
            }
        }
        __syncthreads();

        uint32_t ab = smem_base + s * GR_STAGE + GR_A_OFF;
        uint32_t bb = smem_base + s * GR_STAGE + GR_B_OFF;
#pragma unroll
        for (int ks3 = 0; ks3 < 3; ++ks3) {
            const int ks = wk * 3 + ks3;
            uint32_t a[2][4];
#pragma unroll
            for (int mi = 0; mi < 2; ++mi) {
                uint32_t addr = ab + (warpM * 32 + mi * 16 + lrow) * GR_RB + ks * 32 + lkh * 2;
                ldsm_x4(a[mi][0], a[mi][1], a[mi][2], a[mi][3], addr);
            }
            uint32_t bf[4][2];
#pragma unroll
            for (int nq = 0; nq < 2; ++nq) {
                uint32_t r0, r1, r2, r3;
                uint32_t addr = bb + (warpN * 32 + nq * 16 + lrow) * GR_RB + ks * 32 + lkh * 2;
                ldsm_x4(r0, r1, r2, r3, addr);
                bf[2 * nq][0] = r0;     bf[2 * nq][1] = r2;
                bf[2 * nq + 1][0] = r1; bf[2 * nq + 1][1] = r3;
            }
#pragma unroll
            for (int mi = 0; mi < 2; ++mi)
#pragma unroll
                for (int ni = 0; ni < 4; ++ni)
                    mma_bf16(acc[mi][ni], a[mi], bf[ni]);
        }
        __syncthreads();
        ci = nci;
        s ^= 1;
    }

    atomicAdd(&g_sumsq[b * 128 + cch], ssq);
    atomicAdd(&g_sumsq[b * 128 + 64 + cch], ssv);

    __syncthreads();
    float* red = (float*)sm + (warpM * 2 + warpN) * 1024;
    if (wk == 1) {
#pragma unroll
        for (int mi = 0; mi < 2; ++mi)
#pragma unroll
            for (int ni = 0; ni < 4; ++ni)
#pragma unroll
                for (int r = 0; r < 4; ++r)
                    red[(mi * 16 + ni * 4 + r) * 32 + lane] = acc[mi][ni][r];
    }
    __syncthreads();
    if (wk == 0) {
        const int g = lane >> 2, T = lane & 3;
        float* Gb = g_gram + b * 4096;
#pragma unroll
        for (int mi = 0; mi < 2; ++mi)
#pragma unroll
            for (int ni = 0; ni < 4; ++ni) {
                float r0 = acc[mi][ni][0] + red[(mi * 16 + ni * 4 + 0) * 32 + lane];
                float r1 = acc[mi][ni][1] + red[(mi * 16 + ni * 4 + 1) * 32 + lane];
                float r2 = acc[mi][ni][2] + red[(mi * 16 + ni * 4 + 2) * 32 + lane];
                float r3 = acc[mi][ni][3] + red[(mi * 16 + ni * 4 + 3) * 32 + lane];
                int m = warpM * 32 + mi * 16 + g;
                int n = warpN * 32 + ni * 8 + T * 2;
                atomicAdd(&Gb[m * 64 + n],           r0);
                atomicAdd(&Gb[m * 64 + n + 1],       r1);
                atomicAdd(&Gb[(m + 8) * 64 + n],     r2);
                atomicAdd(&Gb[(m + 8) * 64 + n + 1], r3);
            }
    }
}

// ---------------- norms + softmax + M = w_out @ attn (writes split M) --------
__global__ __launch_bounds__(256) void attn_kernel(
    const float* __restrict__ w_out, const float* __restrict__ temp_p)
{
    __shared__ float attn_s[64 * 65];
    __shared__ float wo_s[64 * 65];
    __shared__ float nrm[128];
    const int tid = threadIdx.x, b = blockIdx.x;

    if (tid < 128) nrm[tid] = fmaxf(sqrtf(g_sumsq[b * 128 + tid]), 1e-12f);
    for (int e = tid; e < 4096; e += 256) {
        int o = e >> 6, c = e & 63;
        wo_s[c * 65 + o] = w_out[e];
    }
    __syncthreads();

    const float temp = *temp_p;
    if (tid < 64) {
        int c = tid;
        float inq = temp / nrm[c];
        float mx = -1e30f;
        for (int d = 0; d < 64; ++d) {
            float l = g_gram[b * 4096 + c * 64 + d] * (inq / nrm[64 + d]);
            attn_s[c * 65 + d] = l;
            mx = fmaxf(mx, l);
        }
        float sum = 0.f;
        for (int d = 0; d < 64; ++d) {
            float e_ = expf(attn_s[c * 65 + d] - mx);
            attn_s[c * 65 + d] = e_;
            sum += e_;
        }
        float inv = 1.f / sum;
        for (int d = 0; d < 64; ++d) attn_s[c * 65 + d] *= inv;
    }
    __syncthreads();

    const int o = tid & 63, dg = tid >> 6;
    for (int d = dg * 16; d < dg * 16 + 16; ++d) {
        float m = 0.f;
#pragma unroll 8
        for (int c2 = 0; c2 < 64; ++c2) m += wo_s[c2 * 65 + o] * attn_s[c2 * 65 + d];
        __nv_bfloat16 hi = __float2bfloat16(m);
        __nv_bfloat16 lo = __float2bfloat16(m - __bfloat162float(hi));
        __nv_bfloat16* dst = g_M2 + ((size_t)b * 64 + o) * 192 + 3 * d;
        dst[0] = hi; dst[1] = hi; dst[2] = lo;
    }
}

// ---------------- tensor-core gemm2: out = M @ v (round-13 exact) ------------
#define G2_A_RB   400
#define G2_A_ARR  (64 * G2_A_RB)
#define G2_B_RB   112
#define G2_B_ARR  (128 * G2_B_RB)
#define G2_X_RB   528
#define G2_X_ARR  (16 * G2_X_RB)
#define G2_STAGE  (G2_B_ARR + G2_X_ARR)
#define G2_SMEM   (G2_A_ARR + 2 * G2_STAGE)
__global__ __launch_bounds__(256, 2) void gemm2_mma(float* __restrict__ out)
{
    extern __shared__ char sm[];
    const int tid = threadIdx.x, wid = tid >> 5, lane = tid & 31;
    const int pbase = blockIdx.x * 128;
    const int b = blockIdx.y;
    const int warpM = wid & 1, warpN = wid >> 1;

    const uint32_t smem_base = smem_to_u32(sm);
    const char*  Agl = (const char*)(g_M2 + (size_t)b * 64 * 192);
    const float* vb  = g_qv + (size_t)b * 128 * NPIX + (size_t)64 * NPIX + pbase;

    auto b_base = [&](int s) { return smem_base + G2_A_ARR + s * G2_STAGE; };
    auto x_base = [&](int s) { return smem_base + G2_A_ARR + s * G2_STAGE + G2_B_ARR; };

#pragma unroll
    for (int e = 0; e < 1536; e += 256) {
        int u = e + tid;
        int r = u / 24, sl = u % 24;
        cp16(smem_base + r * G2_A_RB + sl * 16, Agl + r * 384 + sl * 16);
    }
    auto prefetch = [&](int chunk, int s) {
        uint32_t xbs = x_base(s);
#pragma unroll
        for (int e = 0; e < 512; e += 256) {
            int u = e + tid;
            int ch = u >> 5, sl = u & 31;
            cp16(xbs + ch * G2_X_RB + sl * 16,
                 vb + (size_t)(chunk * 16 + ch) * NPIX + sl * 4);
        }
    };
    prefetch(0, 0);
    CP_COMMIT();

    const int lrow = lane & 15;
    const int lkh  = (lane >> 4) * 8;
    const int cv_p = tid & 127;
    const int cv_g = tid >> 7;

    float acc[2][4][4];
#pragma unroll
    for (int mi = 0; mi < 2; ++mi)
#pragma unroll
        for (int ni = 0; ni < 4; ++ni)
#pragma unroll
            for (int r = 0; r < 4; ++r) acc[mi][ni][r] = 0.f;

#pragma unroll
    for (int c = 0; c < 4; ++c) {
        const int s = c & 1;
        if (c < 3) { prefetch(c + 1, s ^ 1); CP_COMMIT(); }
        if (c < 3) CP_WAIT(1); else CP_WAIT(0);
        __syncthreads();

        {
            const float* xs = (const float*)(sm + G2_A_ARR + s * G2_STAGE + G2_B_ARR);
            char* Bs = sm + G2_A_ARR + s * G2_STAGE;
            uint32_t w[12];
#pragma unroll
            for (int i = 0; i < 4; ++i) {
                int cpi = cv_g * 4 + i;
                float x0 = xs[(2 * cpi) * 132 + cv_p];
                float x1 = xs[(2 * cpi + 1) * 132 + cv_p];
                float h0 = __bfloat162float(__float2bfloat16(x0));
                float h1 = __bfloat162float(__float2bfloat16(x1));
                float l0 = x0 - h0, l1 = x1 - h1;
                w[i * 3 + 0] = bfpair(h0, l0);
                w[i * 3 + 1] = bfpair(h0, h1);
                w[i * 3 + 2] = bfpair(l1, h1);
            }
            uint32_t* brow = (uint32_t*)(Bs + cv_p * G2_B_RB) + cv_g * 12;
#pragma unroll
            for (int i = 0; i < 3; ++i)
                *(uint4*)(brow + i * 4) = make_uint4(w[i*4], w[i*4+1], w[i*4+2], w[i*4+3]);
        }
        __syncthreads();

        uint32_t bb = b_base(s);
#pragma unroll
        for (int ksl = 0; ksl < 3; ++ksl) {
            uint32_t a[2][4];
#pragma unroll
            for (int mi = 0; mi < 2; ++mi) {
                uint32_t addr = smem_base + (warpM * 32 + mi * 16 + lrow) * G2_A_RB
                              + c * 96 + ksl * 32 + lkh * 2;
                ldsm_x4(a[mi][0], a[mi][1], a[mi][2], a[mi][3], addr);
            }
            uint32_t bf[4][2];
#pragma unroll
            for (int nq = 0; nq < 2; ++nq) {
                uint32_t r0, r1, r2, r3;
                uint32_t addr = bb + (warpN * 32 + nq * 16 + lrow) * G2_B_RB + ksl * 32 + lkh * 2;
                ldsm_x4(r0, r1, r2, r3, addr);
                bf[2 * nq][0] = r0;     bf[2 * nq][1] = r2;
                bf[2 * nq + 1][0] = r1; bf[2 * nq + 1][1] = r3;
            }
#pragma unroll
            for (int mi = 0; mi < 2; ++mi)
#pragma unroll
                for (int ni = 0; ni < 4; ++ni)
                    mma_bf16(acc[mi][ni], a[mi], bf[ni]);
        }
        __syncthreads();
    }

    const int g = lane >> 2, T = lane & 3;
#pragma unroll
    for (int mi = 0; mi < 2; ++mi) {
        int o = warpM * 32 + mi * 16 + g;
        float* rowp = out + ((size_t)b * 64 + o) * NPIX + pbase + warpN * 32 + T * 2;
#pragma unroll
        for (int ni = 0; ni < 4; ++ni) {
            *(u64*)(rowp + ni * 8) = pack2(acc[mi][ni][0], acc[mi][ni][1]);
            *(u64*)(rowp + ni * 8 + (size_t)8 * NPIX) = pack2(acc[mi][ni][2], acc[mi][ni][3]);
        }
    }
}

// ---------------- launch ------------------------------------------------------
extern "C" void kernel_launch(void* const* d_in, const int* in_sizes, int n_in,
                              void* d_out, int out_size)
{
    const float* x      = (const float*)d_in[0];
    const float* w_in   = (const float*)d_in[1];
    const float* w_dw   = (const float*)d_in[2];
    const float* w_out  = (const float*)d_in[3];
    const float* temp   = (const float*)d_in[4];
    float* out = (float*)d_out;

    cudaFuncSetAttribute(gemm1_half, cudaFuncAttributeMaxDynamicSharedMemorySize, GH_SMEM);
    cudaFuncSetAttribute(gram_mma,   cudaFuncAttributeMaxDynamicSharedMemorySize, GR_SMEM);
    cudaFuncSetAttribute(gemm2_mma,  cudaFuncAttributeMaxDynamicSharedMemorySize, G2_SMEM);

    // weight split + stat zeroing (merged)
    wsplit<<<64, 256>>>(w_in);

    // t = w_in @ x  (tensor cores, half-A resident, 2 CTAs/SM)
    gemm1_half<<<dim3(GH_GRIDX, 2, BATCH), 256, GH_SMEM>>>(x);

    // depthwise conv + gate -> qv (float4)
    conv_mul<<<dim3(8, 128, BATCH), 256>>>(w_dw);

    // gram + sumsq (tensor cores, K-split warps)
    gram_mma<<<dim3(148, BATCH), 256, GR_SMEM>>>();

    // norms, softmax, M = w_out @ attn (+ bf16-split M)
    attn_kernel<<<BATCH, 256>>>(w_out, temp);

    // out = M @ v (tensor cores, fused split)
    gemm2_mma<<<dim3(NPIX / 128, BATCH), 256, G2_SMEM>>>(out);
}

// round 16
// speedup vs baseline: 1.0076x; 1.0076x over previous
#include <cuda_runtime.h>
#include <cuda_bf16.h>
#include <math.h>
#include <stdint.h>

typedef unsigned long long u64;

#define NPIX  65536   // 256*256
#define BATCH 4

// ---------------- scratch (device globals: allocation is forbidden) -----------
__device__ float g_t[(size_t)BATCH * 256 * NPIX];     // 256 MB : t = w_in @ x
__device__ float g_qv[(size_t)BATCH * 128 * NPIX];    // 128 MB : q, v
__device__ __nv_bfloat16 g_a2[256 * 192];             // bf16-split w_in, [o][192]
__device__ __nv_bfloat16 g_M2[BATCH * 64 * 192];      // bf16-split M = w_out@attn
__device__ float g_sumsq[BATCH * 128];
__device__ float g_gram[BATCH * 64 * 64];

// ---------------- helpers -----------------------------------------------------
__device__ __forceinline__ u64 pack2(float x, float y) {
    u64 d;
    asm("mov.b64 %0, {%1, %2};" : "=l"(d) : "f"(x), "f"(y));
    return d;
}
__device__ __forceinline__ uint32_t smem_to_u32(const void* p) {
    uint32_t a;
    asm("{ .reg .u64 t; cvta.to.shared.u64 t, %1; cvt.u32.u64 %0, t; }" : "=r"(a) : "l"(p));
    return a;
}
__device__ __forceinline__ void ldsm_x4(uint32_t& r0, uint32_t& r1, uint32_t& r2, uint32_t& r3,
                                        uint32_t addr) {
    asm volatile("ldmatrix.sync.aligned.m8n8.x4.shared.b16 {%0,%1,%2,%3}, [%4];"
        : "=r"(r0), "=r"(r1), "=r"(r2), "=r"(r3) : "r"(addr));
}
__device__ __forceinline__ void mma_bf16(float* d, const uint32_t* a, const uint32_t* b) {
    asm volatile("mma.sync.aligned.m16n8k16.row.col.f32.bf16.bf16.f32 "
        "{%0,%1,%2,%3}, {%4,%5,%6,%7}, {%8,%9}, {%0,%1,%2,%3};"
        : "+f"(d[0]), "+f"(d[1]), "+f"(d[2]), "+f"(d[3])
        : "r"(a[0]), "r"(a[1]), "r"(a[2]), "r"(a[3]), "r"(b[0]), "r"(b[1]));
}
__device__ __forceinline__ void cp16(uint32_t smem_addr, const void* gptr) {
    asm volatile("cp.async.cg.shared.global [%0], [%1], 16;" :: "r"(smem_addr), "l"(gptr));
}
#define CP_COMMIT() asm volatile("cp.async.commit_group;" ::: "memory")
#define CP_WAIT(n)  asm volatile("cp.async.wait_group %0;" :: "n"(n) : "memory")

__device__ __forceinline__ unsigned short bfbits(float v) {
    __nv_bfloat16 h = __float2bfloat16(v);
    return *(unsigned short*)&h;
}
__device__ __forceinline__ uint32_t bfpair(float a, float b) {
    return (uint32_t)bfbits(a) | ((uint32_t)bfbits(b) << 16);
}

// ---------------- weight split + zero stats (merged) --------------------------
__global__ void wsplit(const float* __restrict__ w_in) {
    const int gi = threadIdx.x + blockIdx.x * blockDim.x;
    const int gs = blockDim.x * gridDim.x;
    for (int i = gi; i < 256 * 192; i += gs) {
        int o = i / 192, k = i % 192;
        int c = k / 3, j = k % 3;
        float w = w_in[o * 64 + c];
        __nv_bfloat16 hi = __float2bfloat16(w);
        if (j == 2) g_a2[i] = __float2bfloat16(w - __bfloat162float(hi));
        else        g_a2[i] = hi;
    }
    for (int i = gi; i < BATCH * 128 + BATCH * 64 * 64; i += gs) {
        if (i < BATCH * 128) g_sumsq[i] = 0.f;
        else                 g_gram[i - BATCH * 128] = 0.f;
    }
}

// ---------------- A-resident tensor-core gemm1, 128-px tiles ------------------
// t = w_in @ x, bf16-split K=192. A (256x192) staged ONCE (100KB);
// tile = 256 outs x 128 px; X (64ch x 128px fp32) double-buffered + convert.
// 512 threads = 16 warps = 8(m:32) x 2(n:64). grid (37,1,BATCH), 1 CTA/SM.
#define GA_RB     400
#define GA_A_ARR  (256 * GA_RB)                // 102400
#define GA_B_ARR  (128 * GA_RB)                // 51200
#define GA_X_RB   528                          // 128px*4B=512 data +16 pad
#define GA_X_ARR  (64 * GA_X_RB)               // 33792
#define GA_B_OFF  GA_A_ARR
#define GA_X_OFF  (GA_A_ARR + GA_B_ARR)
#define GA_SMEM   (GA_A_ARR + GA_B_ARR + 2 * GA_X_ARR)   // 221184
#define GA_NTILE  512                          // NPIX / 128
#define GA_GRIDX  37
__global__ __launch_bounds__(512, 1) void gemm1_res(const float* __restrict__ x) {
    extern __shared__ char sm[];
    const int tid = threadIdx.x, wid = tid >> 5, lane = tid & 31;
    const int b = blockIdx.z;
    const int wm = wid & 7, wn = wid >> 3;

    const uint32_t smem_base = smem_to_u32(sm);
    const char*  Agl = (const char*)g_a2;
    const float* xb  = x + (size_t)b * 64 * NPIX;

    // stage A once: 256 rows x 24 slabs of 16B
#pragma unroll
    for (int e = 0; e < 6144; e += 512) {
        int u = e + tid;
        int r = u / 24, sl = u % 24;
        cp16(smem_base + r * GA_RB + sl * 16, Agl + r * 384 + sl * 16);
    }

    auto prefetch_x = [&](int t, int s) {
        uint32_t xbs = smem_base + GA_X_OFF + s * GA_X_ARR;
        const float* src = xb + t * 128;
        // 64 ch x 32 slabs = 2048 units, 4 per thread
#pragma unroll
        for (int e = 0; e < 2048; e += 512) {
            int u = e + tid;
            int ch = u >> 5, sl = u & 31;
            cp16(xbs + ch * GA_X_RB + sl * 16, src + (size_t)ch * NPIX + sl * 4);
        }
    };

    const int lrow = lane & 15;
    const int lkh  = (lane >> 4) * 8;
    const int g = lane >> 2, T = lane & 3;
    const int cp_p  = tid & 127;     // convert pixel
    const int cp_g0 = tid >> 7;      // convert groups cp_g0, cp_g0+4

    int t = blockIdx.x;
    int s = 0;
    prefetch_x(t, 0);
    CP_COMMIT();

    while (t < GA_NTILE) {
        const int nt = t + GA_GRIDX;
        if (nt < GA_NTILE) { prefetch_x(nt, s ^ 1); CP_COMMIT(); CP_WAIT(1); }
        else               { CP_WAIT(0); }
        __syncthreads();

        // convert raw x[s] -> B: 2 units/thread (pixel, 4 channel-pairs each)
        {
            const float* xs = (const float*)(sm + GA_X_OFF + s * GA_X_ARR);
#pragma unroll
            for (int gsel = 0; gsel < 2; ++gsel) {
                int cg = cp_g0 + gsel * 4;
                uint32_t* brow = (uint32_t*)(sm + GA_B_OFF + cp_p * GA_RB) + cg * 12;
                uint32_t w[12];
#pragma unroll
                for (int i = 0; i < 4; ++i) {
                    int cpi = cg * 4 + i;
                    float x0 = xs[(2 * cpi) * 132 + cp_p];
                    float x1 = xs[(2 * cpi + 1) * 132 + cp_p];
                    float h0 = __bfloat162float(__float2bfloat16(x0));
                    float h1 = __bfloat162float(__float2bfloat16(x1));
                    float l0 = x0 - h0, l1 = x1 - h1;
                    w[i * 3 + 0] = bfpair(h0, l0);
                    w[i * 3 + 1] = bfpair(h0, h1);
                    w[i * 3 + 2] = bfpair(l1, h1);
                }
#pragma unroll
                for (int i = 0; i < 3; ++i)
                    *(uint4*)(brow + i * 4) = make_uint4(w[i*4], w[i*4+1], w[i*4+2], w[i*4+3]);
            }
        }
        __syncthreads();

        float acc[2][8][4];
#pragma unroll
        for (int mi = 0; mi < 2; ++mi)
#pragma unroll
            for (int ni = 0; ni < 8; ++ni)
#pragma unroll
                for (int r = 0; r < 4; ++r) acc[mi][ni][r] = 0.f;

        uint32_t bb = smem_base + GA_B_OFF;
#pragma unroll
        for (int ks = 0; ks < 12; ++ks) {
            uint32_t a[2][4];
#pragma unroll
            for (int mi = 0; mi < 2; ++mi) {
                uint32_t addr = smem_base + (wm * 32 + mi * 16 + lrow) * GA_RB + ks * 32 + lkh * 2;
                ldsm_x4(a[mi][0], a[mi][1], a[mi][2], a[mi][3], addr);
            }
            uint32_t bf[8][2];
#pragma unroll
            for (int nq = 0; nq < 4; ++nq) {
                uint32_t r0, r1, r2, r3;
                uint32_t addr = bb + (wn * 64 + nq * 16 + lrow) * GA_RB + ks * 32 + lkh * 2;
                ldsm_x4(r0, r1, r2, r3, addr);
                bf[2 * nq][0] = r0;     bf[2 * nq][1] = r2;
                bf[2 * nq + 1][0] = r1; bf[2 * nq + 1][1] = r3;
            }
#pragma unroll
            for (int mi = 0; mi < 2; ++mi)
#pragma unroll
                for (int ni = 0; ni < 8; ++ni)
                    mma_bf16(acc[mi][ni], a[mi], bf[ni]);
        }
        __syncthreads();   // B + X[s] reuse protection

        // epilogue: thread holds rows g,g+8; cols T*2,T*2+1 (+8*ni)
#pragma unroll
        for (int mi = 0; mi < 2; ++mi) {
            int m = wm * 32 + mi * 16 + g;
            float* rowp = g_t + ((size_t)b * 256 + m) * NPIX + t * 128 + wn * 64 + T * 2;
#pragma unroll
            for (int ni = 0; ni < 8; ++ni) {
                *(u64*)(rowp + ni * 8) = pack2(acc[mi][ni][0], acc[mi][ni][1]);
                *(u64*)(rowp + ni * 8 + (size_t)8 * NPIX) = pack2(acc[mi][ni][2], acc[mi][ni][3]);
            }
        }
        t = nt;
        s ^= 1;
    }
}

// ---------------- depthwise 3x3 conv + gate, float4 (round-9 exact) ----------
__global__ __launch_bounds__(256) void conv_mul(const float* __restrict__ w_dw)
{
    __shared__ float st[34][264];
    const int tid = threadIdx.x;
    const int jj = blockIdx.y, b = blockIdx.z, r0 = blockIdx.x * 32;

    const float* t1 = g_t + ((size_t)b * 256 + jj) * NPIX;
    const float* t2 = g_t + ((size_t)b * 256 + 128 + jj) * NPIX;
    float* outp = g_qv + ((size_t)b * 128 + jj) * NPIX;

    float wd[9];
#pragma unroll
    for (int i = 0; i < 9; ++i) wd[i] = w_dw[jj * 9 + i];

#pragma unroll
    for (int e = 0; e < 2176; e += 256) {
        int u = e + tid;
        if (u < 2176) {
            int rr = u >> 6, q4 = u & 63;
            int row = r0 - 1 + rr;
            float4 v = make_float4(0.f, 0.f, 0.f, 0.f);
            if (row >= 0 && row < 256)
                v = *(const float4*)(t1 + row * 256 + q4 * 4);
            *(float4*)&st[rr][4 + q4 * 4] = v;
        }
    }
    if (tid < 34) { st[tid][3] = 0.f; st[tid][260] = 0.f; }
    __syncthreads();

    const int ty = tid >> 6, tc = tid & 63;
    const int c0 = tc * 4;
#pragma unroll
    for (int r = ty * 8; r < ty * 8 + 8; ++r) {
        float s0 = 0.f, s1 = 0.f, s2 = 0.f, s3 = 0.f;
#pragma unroll
        for (int ky = 0; ky < 3; ++ky) {
            const float* rowp = &st[r + ky][4 + c0];
            float4 m = *(const float4*)rowp;
            float left = rowp[-1], right = rowp[4];
            float w0 = wd[ky * 3 + 0], w1 = wd[ky * 3 + 1], w2 = wd[ky * 3 + 2];
            s0 += w0 * left + w1 * m.x + w2 * m.y;
            s1 += w0 * m.x  + w1 * m.y + w2 * m.z;
            s2 += w0 * m.y  + w1 * m.z + w2 * m.w;
            s3 += w0 * m.z  + w1 * m.w + w2 * right;
        }
        int p = (r0 + r) * 256 + c0;
        float4 g4 = *(const float4*)(t2 + p);
        float4 o = make_float4(s0 * g4.x, s1 * g4.y, s2 * g4.z, s3 * g4.w);
        *(float4*)(outp + p) = o;
    }
}

// ---------------- tensor-core gram + sumsq (round-14 exact) -------------------
#define GR_RB     208
#define GR_XRB    144
#define GR_A_OFF  0
#define GR_B_OFF  13312
#define GR_Q_OFF  26624
#define GR_V_OFF  35840
#define GR_STAGE  45056
#define GR_SMEM   (2 * GR_STAGE)
#define GR_NCHUNK 2048
__global__ __launch_bounds__(256, 2) void gram_mma()
{
    extern __shared__ char sm[];
    const int tid = threadIdx.x, wid = tid >> 5, lane = tid & 31;
    const int b = blockIdx.y;
    const int wk = wid >> 2;
    const int warpM = wid & 1, warpN = (wid >> 1) & 1;

    const uint32_t smem_base = smem_to_u32(sm);
    const float* qsrc = g_qv + (size_t)b * 128 * NPIX;
    const float* vsrc = qsrc + (size_t)64 * NPIX;

    auto prefetch = [&](int ci, int s) {
        int pbase = ci * 32;
        uint32_t qb = smem_base + s * GR_STAGE + GR_Q_OFF;
        uint32_t vb = smem_base + s * GR_STAGE + GR_V_OFF;
#pragma unroll
        for (int e = 0; e < 512; e += 256) {
            int u = e + tid;
            int ch = u >> 3, sl = u & 7;
            cp16(qb + ch * GR_XRB + sl * 16, qsrc + (size_t)ch * NPIX + pbase + sl * 4);
        }
#pragma unroll
        for (int e = 0; e < 512; e += 256) {
            int u = e + tid;
            int ch = u >> 3, sl = u & 7;
            cp16(vb + ch * GR_XRB + sl * 16, vsrc + (size_t)ch * NPIX + pbase + sl * 4);
        }
    };

    const int lrow = lane & 15;
    const int lkh  = (lane >> 4) * 8;

    float acc[2][4][4];
#pragma unroll
    for (int mi = 0; mi < 2; ++mi)
#pragma unroll
        for (int ni = 0; ni < 4; ++ni)
#pragma unroll
            for (int r = 0; r < 4; ++r) acc[mi][ni][r] = 0.f;
    float ssq = 0.f, ssv = 0.f;

    const int cch = tid >> 2;
    const int ppr = (tid & 3) * 4;

    int ci = blockIdx.x;
    int s = 0;
    prefetch(ci, 0);
    CP_COMMIT();

    while (ci < GR_NCHUNK) {
        const int nci = ci + gridDim.x;
        const bool more = nci < GR_NCHUNK;
        if (more) { prefetch(nci, s ^ 1); CP_COMMIT(); CP_WAIT(1); }
        else      { CP_WAIT(0); }
        __syncthreads();

        {
            const float* rq = (const float*)(sm + s * GR_STAGE + GR_Q_OFF) + cch * 36 + ppr * 2;
            const float* rv = (const float*)(sm + s * GR_STAGE + GR_V_OFF) + cch * 36 + ppr * 2;
            float4 qa = *(const float4*)rq, qb4 = *(const float4*)(rq + 4);
            float4 va = *(const float4*)rv, vb4 = *(const float4*)(rv + 4);
            float qq[8] = {qa.x, qa.y, qa.z, qa.w, qb4.x, qb4.y, qb4.z, qb4.w};
            float vv[8] = {va.x, va.y, va.z, va.w, vb4.x, vb4.y, vb4.z, vb4.w};
            uint32_t wq[12], wv[12];
#pragma unroll
            for (int pr = 0; pr < 4; ++pr) {
                float q0 = qq[2 * pr], q1 = qq[2 * pr + 1];
                float v0 = vv[2 * pr], v1 = vv[2 * pr + 1];
                ssq += q0 * q0 + q1 * q1;
                ssv += v0 * v0 + v1 * v1;
                float qh0 = __bfloat162float(__float2bfloat16(q0));
                float qh1 = __bfloat162float(__float2bfloat16(q1));
                float vh0 = __bfloat162float(__float2bfloat16(v0));
                float vh1 = __bfloat162float(__float2bfloat16(v1));
                float ql0 = q0 - qh0, ql1 = q1 - qh1;
                float vl0 = v0 - vh0, vl1 = v1 - vh1;
                wq[pr * 3 + 0] = bfpair(qh0, qh0);
                wq[pr * 3 + 1] = bfpair(ql0, qh1);
                wq[pr * 3 + 2] = bfpair(qh1, ql1);
                wv[pr * 3 + 0] = bfpair(vh0, vl0);
                wv[pr * 3 + 1] = bfpair(vh0, vh1);
                wv[pr * 3 + 2] = bfpair(vl1, vh1);
            }
            uint32_t* aq = (uint32_t*)(sm + s * GR_STAGE + GR_A_OFF + cch * GR_RB) + ppr * 3;
            uint32_t* bv = (uint32_t*)(sm + s * GR_STAGE + GR_B_OFF + cch * GR_RB) + ppr * 3;
#pragma unroll
            for (int i = 0; i < 3; ++i) {
                *(uint4*)(aq + i * 4) = make_uint4(wq[i*4], wq[i*4+1], wq[i*4+2], wq[i*4+3]);
                *(uint4*)(bv + i * 4) = make_uint4(wv[i*4], wv[i*4+1], wv[i*4+2], wv[i*4+3]);
            }
        }
        __syncthreads();

        uint32_t ab = smem_base + s * GR_STAGE + GR_A_OFF;
        uint32_t bb = smem_base + s * GR_STAGE + GR_B_OFF;
#pragma unroll
        for (int ks3 = 0; ks3 < 3; ++ks3) {
            const int ks = wk * 3 + ks3;
            uint32_t a[2][4];
#pragma unroll
            for (int mi = 0; mi < 2; ++mi) {
                uint32_t addr = ab + (warpM * 32 + mi * 16 + lrow) * GR_RB + ks * 32 + lkh * 2;
                ldsm_x4(a[mi][0], a[mi][1], a[mi][2], a[mi][3], addr);
            }
            uint32_t bf[4][2];
#pragma unroll
            for (int nq = 0; nq < 2; ++nq) {
                uint32_t r0, r1, r2, r3;
                uint32_t addr = bb + (warpN * 32 + nq * 16 + lrow) * GR_RB + ks * 32 + lkh * 2;
                ldsm_x4(r0, r1, r2, r3, addr);
                bf[2 * nq][0] = r0;     bf[2 * nq][1] = r2;
                bf[2 * nq + 1][0] = r1; bf[2 * nq + 1][1] = r3;
            }
#pragma unroll
            for (int mi = 0; mi < 2; ++mi)
#pragma unroll
                for (int ni = 0; ni < 4; ++ni)
                    mma_bf16(acc[mi][ni], a[mi], bf[ni]);
        }
        __syncthreads();
        ci = nci;
        s ^= 1;
    }

    atomicAdd(&g_sumsq[b * 128 + cch], ssq);
    atomicAdd(&g_sumsq[b * 128 + 64 + cch], ssv);

    __syncthreads();
    float* red = (float*)sm + (warpM * 2 + warpN) * 1024;
    if (wk == 1) {
#pragma unroll
        for (int mi = 0; mi < 2; ++mi)
#pragma unroll
            for (int ni = 0; ni < 4; ++ni)
#pragma unroll
                for (int r = 0; r < 4; ++r)
                    red[(mi * 16 + ni * 4 + r) * 32 + lane] = acc[mi][ni][r];
    }
    __syncthreads();
    if (wk == 0) {
        const int g = lane >> 2, T = lane & 3;
        float* Gb = g_gram + b * 4096;
#pragma unroll
        for (int mi = 0; mi < 2; ++mi)
#pragma unroll
            for (int ni = 0; ni < 4; ++ni) {
                float r0 = acc[mi][ni][0] + red[(mi * 16 + ni * 4 + 0) * 32 + lane];
                float r1 = acc[mi][ni][1] + red[(mi * 16 + ni * 4 + 1) * 32 + lane];
                float r2 = acc[mi][ni][2] + red[(mi * 16 + ni * 4 + 2) * 32 + lane];
                float r3 = acc[mi][ni][3] + red[(mi * 16 + ni * 4 + 3) * 32 + lane];
                int m = warpM * 32 + mi * 16 + g;
                int n = warpN * 32 + ni * 8 + T * 2;
                atomicAdd(&Gb[m * 64 + n],           r0);
                atomicAdd(&Gb[m * 64 + n + 1],       r1);
                atomicAdd(&Gb[(m + 8) * 64 + n],     r2);
                atomicAdd(&Gb[(m + 8) * 64 + n + 1], r3);
            }
    }
}

// ---------------- norms + softmax + M = w_out @ attn (writes split M) --------
__global__ __launch_bounds__(256) void attn_kernel(
    const float* __restrict__ w_out, const float* __restrict__ temp_p)
{
    __shared__ float attn_s[64 * 65];
    __shared__ float wo_s[64 * 65];
    __shared__ float nrm[128];
    const int tid = threadIdx.x, b = blockIdx.x;

    if (tid < 128) nrm[tid] = fmaxf(sqrtf(g_sumsq[b * 128 + tid]), 1e-12f);
    for (int e = tid; e < 4096; e += 256) {
        int o = e >> 6, c = e & 63;
        wo_s[c * 65 + o] = w_out[e];
    }
    __syncthreads();

    const float temp = *temp_p;
    if (tid < 64) {
        int c = tid;
        float inq = temp / nrm[c];
        float mx = -1e30f;
        for (int d = 0; d < 64; ++d) {
            float l = g_gram[b * 4096 + c * 64 + d] * (inq / nrm[64 + d]);
            attn_s[c * 65 + d] = l;
            mx = fmaxf(mx, l);
        }
        float sum = 0.f;
        for (int d = 0; d < 64; ++d) {
            float e_ = expf(attn_s[c * 65 + d] - mx);
            attn_s[c * 65 + d] = e_;
            sum += e_;
        }
        float inv = 1.f / sum;
        for (int d = 0; d < 64; ++d) attn_s[c * 65 + d] *= inv;
    }
    __syncthreads();

    const int o = tid & 63, dg = tid >> 6;
    for (int d = dg * 16; d < dg * 16 + 16; ++d) {
        float m = 0.f;
#pragma unroll 8
        for (int c2 = 0; c2 < 64; ++c2) m += wo_s[c2 * 65 + o] * attn_s[c2 * 65 + d];
        __nv_bfloat16 hi = __float2bfloat16(m);
        __nv_bfloat16 lo = __float2bfloat16(m - __bfloat162float(hi));
        __nv_bfloat16* dst = g_M2 + ((size_t)b * 64 + o) * 192 + 3 * d;
        dst[0] = hi; dst[1] = hi; dst[2] = lo;
    }
}

// ---------------- tensor-core gemm2: out = M @ v (round-13 exact) ------------
#define G2_A_RB   400
#define G2_A_ARR  (64 * G2_A_RB)
#define G2_B_RB   112
#define G2_B_ARR  (128 * G2_B_RB)
#define G2_X_RB   528
#define G2_X_ARR  (16 * G2_X_RB)
#define G2_STAGE  (G2_B_ARR + G2_X_ARR)
#define G2_SMEM   (G2_A_ARR + 2 * G2_STAGE)
__global__ __launch_bounds__(256, 2) void gemm2_mma(float* __restrict__ out)
{
    extern __shared__ char sm[];
    const int tid = threadIdx.x, wid = tid >> 5, lane = tid & 31;
    const int pbase = blockIdx.x * 128;
    const int b = blockIdx.y;
    const int warpM = wid & 1, warpN = wid >> 1;

    const uint32_t smem_base = smem_to_u32(sm);
    const char*  Agl = (const char*)(g_M2 + (size_t)b * 64 * 192);
    const float* vb  = g_qv + (size_t)b * 128 * NPIX + (size_t)64 * NPIX + pbase;

    auto b_base = [&](int s) { return smem_base + G2_A_ARR + s * G2_STAGE; };
    auto x_base = [&](int s) { return smem_base + G2_A_ARR + s * G2_STAGE + G2_B_ARR; };

#pragma unroll
    for (int e = 0; e < 1536; e += 256) {
        int u = e + tid;
        int r = u / 24, sl = u % 24;
        cp16(smem_base + r * G2_A_RB + sl * 16, Agl + r * 384 + sl * 16);
    }
    auto prefetch = [&](int chunk, int s) {
        uint32_t xbs = x_base(s);
#pragma unroll
        for (int e = 0; e < 512; e += 256) {
            int u = e + tid;
            int ch = u >> 5, sl = u & 31;
            cp16(xbs + ch * G2_X_RB + sl * 16,
                 vb + (size_t)(chunk * 16 + ch) * NPIX + sl * 4);
        }
    };
    prefetch(0, 0);
    CP_COMMIT();

    const int lrow = lane & 15;
    const int lkh  = (lane >> 4) * 8;
    const int cv_p = tid & 127;
    const int cv_g = tid >> 7;

    float acc[2][4][4];
#pragma unroll
    for (int mi = 0; mi < 2; ++mi)
#pragma unroll
        for (int ni = 0; ni < 4; ++ni)
#pragma unroll
            for (int r = 0; r < 4; ++r) acc[mi][ni][r] = 0.f;

#pragma unroll
    for (int c = 0; c < 4; ++c) {
        const int s = c & 1;
        if (c < 3) { prefetch(c + 1, s ^ 1); CP_COMMIT(); }
        if (c < 3) CP_WAIT(1); else CP_WAIT(0);
        __syncthreads();

        {
            const float* xs = (const float*)(sm + G2_A_ARR + s * G2_STAGE + G2_B_ARR);
            char* Bs = sm + G2_A_ARR + s * G2_STAGE;
            uint32_t w[12];
#pragma unroll
            for (int i = 0; i < 4; ++i) {
                int cpi = cv_g * 4 + i;
                float x0 = xs[(2 * cpi) * 132 + cv_p];
                float x1 = xs[(2 * cpi + 1) * 132 + cv_p];
                float h0 = __bfloat162float(__float2bfloat16(x0));
                float h1 = __bfloat162float(__float2bfloat16(x1));
                float l0 = x0 - h0, l1 = x1 - h1;
                w[i * 3 + 0] = bfpair(h0, l0);
                w[i * 3 + 1] = bfpair(h0, h1);
                w[i * 3 + 2] = bfpair(l1, h1);
            }
            uint32_t* brow = (uint32_t*)(Bs + cv_p * G2_B_RB) + cv_g * 12;
#pragma unroll
            for (int i = 0; i < 3; ++i)
                *(uint4*)(brow + i * 4) = make_uint4(w[i*4], w[i*4+1], w[i*4+2], w[i*4+3]);
        }
        __syncthreads();

        uint32_t bb = b_base(s);
#pragma unroll
        for (int ksl = 0; ksl < 3; ++ksl) {
            uint32_t a[2][4];
#pragma unroll
            for (int mi = 0; mi < 2; ++mi) {
                uint32_t addr = smem_base + (warpM * 32 + mi * 16 + lrow) * G2_A_RB
                              + c * 96 + ksl * 32 + lkh * 2;
                ldsm_x4(a[mi][0], a[mi][1], a[mi][2], a[mi][3], addr);
            }
            uint32_t bf[4][2];
#pragma unroll
            for (int nq = 0; nq < 2; ++nq) {
                uint32_t r0, r1, r2, r3;
                uint32_t addr = bb + (warpN * 32 + nq * 16 + lrow) * G2_B_RB + ksl * 32 + lkh * 2;
                ldsm_x4(r0, r1, r2, r3, addr);
                bf[2 * nq][0] = r0;     bf[2 * nq][1] = r2;
                bf[2 * nq + 1][0] = r1; bf[2 * nq + 1][1] = r3;
            }
#pragma unroll
            for (int mi = 0; mi < 2; ++mi)
#pragma unroll
                for (int ni = 0; ni < 4; ++ni)
                    mma_bf16(acc[mi][ni], a[mi], bf[ni]);
        }
        __syncthreads();
    }

    const int g = lane >> 2, T = lane & 3;
#pragma unroll
    for (int mi = 0; mi < 2; ++mi) {
        int o = warpM * 32 + mi * 16 + g;
        float* rowp = out + ((size_t)b * 64 + o) * NPIX + pbase + warpN * 32 + T * 2;
#pragma unroll
        for (int ni = 0; ni < 4; ++ni) {
            *(u64*)(rowp + ni * 8) = pack2(acc[mi][ni][0], acc[mi][ni][1]);
            *(u64*)(rowp + ni * 8 + (size_t)8 * NPIX) = pack2(acc[mi][ni][2], acc[mi][ni][3]);
        }
    }
}

// ---------------- launch ------------------------------------------------------
extern "C" void kernel_launch(void* const* d_in, const int* in_sizes, int n_in,
                              void* d_out, int out_size)
{
    const float* x      = (const float*)d_in[0];
    const float* w_in   = (const float*)d_in[1];
    const float* w_dw   = (const float*)d_in[2];
    const float* w_out  = (const float*)d_in[3];
    const float* temp   = (const float*)d_in[4];
    float* out = (float*)d_out;

    cudaFuncSetAttribute(gemm1_res, cudaFuncAttributeMaxDynamicSharedMemorySize, GA_SMEM);
    cudaFuncSetAttribute(gram_mma,  cudaFuncAttributeMaxDynamicSharedMemorySize, GR_SMEM);
    cudaFuncSetAttribute(gemm2_mma, cudaFuncAttributeMaxDynamicSharedMemorySize, G2_SMEM);

    // weight split + stat zeroing (merged)
    wsplit<<<64, 256>>>(w_in);

    // t = w_in @ x  (tensor cores, A-resident, 128-px tiles)
    gemm1_res<<<dim3(GA_GRIDX, 1, BATCH), 512, GA_SMEM>>>(x);

    // depthwise conv + gate -> qv (float4)
    conv_mul<<<dim3(8, 128, BATCH), 256>>>(w_dw);

    // gram + sumsq (tensor cores, K-split warps)
    gram_mma<<<dim3(148, BATCH), 256, GR_SMEM>>>();

    // norms, softmax, M = w_out @ attn (+ bf16-split M)
    attn_kernel<<<BATCH, 256>>>(w_out, temp);

    // out = M @ v (tensor cores, fused split)
    gemm2_mma<<<dim3(NPIX / 128, BATCH), 256, G2_SMEM>>>(out);
}

// round 17
// speedup vs baseline: 1.0390x; 1.0312x over previous
#include <cuda_runtime.h>
#include <cuda_bf16.h>
#include <math.h>
#include <stdint.h>

typedef unsigned long long u64;

#define NPIX  65536   // 256*256
#define BATCH 4

// ---------------- scratch (device globals: allocation is forbidden) -----------
__device__ float g_t[(size_t)BATCH * 256 * NPIX];     // 256 MB : t = w_in @ x
__device__ float g_qv[(size_t)BATCH * 128 * NPIX];    // 128 MB : q, v
__device__ __nv_bfloat16 g_a2[256 * 192];             // bf16-split w_in, [o][192]
__device__ __nv_bfloat16 g_M2[BATCH * 64 * 192];      // bf16-split M = w_out@attn
__device__ float g_sumsq[BATCH * 128];
__device__ float g_gram[BATCH * 64 * 64];

// ---------------- helpers -----------------------------------------------------
__device__ __forceinline__ u64 pack2(float x, float y) {
    u64 d;
    asm("mov.b64 %0, {%1, %2};" : "=l"(d) : "f"(x), "f"(y));
    return d;
}
__device__ __forceinline__ uint32_t smem_to_u32(const void* p) {
    uint32_t a;
    asm("{ .reg .u64 t; cvta.to.shared.u64 t, %1; cvt.u32.u64 %0, t; }" : "=r"(a) : "l"(p));
    return a;
}
__device__ __forceinline__ void ldsm_x4(uint32_t& r0, uint32_t& r1, uint32_t& r2, uint32_t& r3,
                                        uint32_t addr) {
    asm volatile("ldmatrix.sync.aligned.m8n8.x4.shared.b16 {%0,%1,%2,%3}, [%4];"
        : "=r"(r0), "=r"(r1), "=r"(r2), "=r"(r3) : "r"(addr));
}
__device__ __forceinline__ void mma_bf16(float* d, const uint32_t* a, const uint32_t* b) {
    asm volatile("mma.sync.aligned.m16n8k16.row.col.f32.bf16.bf16.f32 "
        "{%0,%1,%2,%3}, {%4,%5,%6,%7}, {%8,%9}, {%0,%1,%2,%3};"
        : "+f"(d[0]), "+f"(d[1]), "+f"(d[2]), "+f"(d[3])
        : "r"(a[0]), "r"(a[1]), "r"(a[2]), "r"(a[3]), "r"(b[0]), "r"(b[1]));
}
__device__ __forceinline__ void cp16(uint32_t smem_addr, const void* gptr) {
    asm volatile("cp.async.cg.shared.global [%0], [%1], 16;" :: "r"(smem_addr), "l"(gptr));
}
#define CP_COMMIT() asm volatile("cp.async.commit_group;" ::: "memory")
#define CP_WAIT(n)  asm volatile("cp.async.wait_group %0;" :: "n"(n) : "memory")

__device__ __forceinline__ unsigned short bfbits(float v) {
    __nv_bfloat16 h = __float2bfloat16(v);
    return *(unsigned short*)&h;
}
__device__ __forceinline__ uint32_t bfpair(float a, float b) {
    return (uint32_t)bfbits(a) | ((uint32_t)bfbits(b) << 16);
}

// ---------------- weight split + zero stats (merged) --------------------------
__global__ void wsplit(const float* __restrict__ w_in) {
    const int gi = threadIdx.x + blockIdx.x * blockDim.x;
    const int gs = blockDim.x * gridDim.x;
    for (int i = gi; i < 256 * 192; i += gs) {
        int o = i / 192, k = i % 192;
        int c = k / 3, j = k % 3;
        float w = w_in[o * 64 + c];
        __nv_bfloat16 hi = __float2bfloat16(w);
        if (j == 2) g_a2[i] = __float2bfloat16(w - __bfloat162float(hi));
        else        g_a2[i] = hi;
    }
    for (int i = gi; i < BATCH * 128 + BATCH * 64 * 64; i += gs) {
        if (i < BATCH * 128) g_sumsq[i] = 0.f;
        else                 g_gram[i - BATCH * 128] = 0.f;
    }
}

// ---------------- A-resident tensor-core gemm1 (single B, 3-stage X ring) ----
#define GA_RB     400
#define GA_A_ARR  (256 * GA_RB)
#define GA_B_ARR  (64 * GA_RB)
#define GA_X_RB   272
#define GA_X_ARR  (64 * GA_X_RB)
#define GA_B_OFF  GA_A_ARR
#define GA_X_OFF  (GA_A_ARR + GA_B_ARR)
#define GA_SMEM   (GA_A_ARR + GA_B_ARR + 3 * GA_X_ARR)   // 180224
#define GA_NTILE  1024
#define GA_GRIDX  37
__global__ __launch_bounds__(512, 1) void gemm1_res(const float* __restrict__ x) {
    extern __shared__ char sm[];
    const int tid = threadIdx.x, wid = tid >> 5, lane = tid & 31;
    const int b = blockIdx.z;
    const int wm = wid & 7, wn = wid >> 3;

    const uint32_t smem_base = smem_to_u32(sm);
    const char*  Agl = (const char*)g_a2;
    const float* xb  = x + (size_t)b * 64 * NPIX;

#pragma unroll
    for (int e = 0; e < 6144; e += 512) {
        int u = e + tid;
        int r = u / 24, sl = u % 24;
        cp16(smem_base + r * GA_RB + sl * 16, Agl + r * 384 + sl * 16);
    }

    auto prefetch_x = [&](int t, int s) {
        uint32_t xbs = smem_base + GA_X_OFF + s * GA_X_ARR;
        const float* src = xb + t * 64;
#pragma unroll
        for (int e = 0; e < 1024; e += 512) {
            int u = e + tid;
            int ch = u >> 4, sl = u & 15;
            cp16(xbs + ch * GA_X_RB + sl * 16, src + (size_t)ch * NPIX + sl * 4);
        }
    };

    const int lrow = lane & 15;
    const int lkh  = (lane >> 4) * 8;
    const int g = lane >> 2, T = lane & 3;
    const int cp_p  = tid & 63;
    const int cp_g  = tid >> 6;

    int t = blockIdx.x;
    int si = 0;
    prefetch_x(t, 0);
    CP_COMMIT();
    if (t + GA_GRIDX < GA_NTILE) { prefetch_x(t + GA_GRIDX, 1); CP_COMMIT(); }

    while (t < GA_NTILE) {
        const int nt = t + GA_GRIDX;
        const int t2 = t + 2 * GA_GRIDX;
        if (nt < GA_NTILE) CP_WAIT(1); else CP_WAIT(0);
        __syncthreads();

        // convert raw x[si] -> B (single buffer; loop-top sync protects reuse)
        {
            const float* xs = (const float*)(sm + GA_X_OFF + si * GA_X_ARR);
            uint32_t* brow = (uint32_t*)(sm + GA_B_OFF + cp_p * GA_RB) + cp_g * 12;
            uint32_t w[12];
#pragma unroll
            for (int i = 0; i < 4; ++i) {
                int cpi = cp_g * 4 + i;
                float x0 = xs[(2 * cpi) * 68 + cp_p];
                float x1 = xs[(2 * cpi + 1) * 68 + cp_p];
                float h0 = __bfloat162float(__float2bfloat16(x0));
                float h1 = __bfloat162float(__float2bfloat16(x1));
                float l0 = x0 - h0, l1 = x1 - h1;
                w[i * 3 + 0] = bfpair(h0, l0);
                w[i * 3 + 1] = bfpair(h0, h1);
                w[i * 3 + 2] = bfpair(l1, h1);
            }
#pragma unroll
            for (int i = 0; i < 3; ++i)
                *(uint4*)(brow + i * 4) = make_uint4(w[i*4], w[i*4+1], w[i*4+2], w[i*4+3]);
        }
        __syncthreads();

        if (t2 < GA_NTILE) {
            int s2 = si + 2; if (s2 >= 3) s2 -= 3;
            prefetch_x(t2, s2); CP_COMMIT();
        }

        float acc[2][4][4];
#pragma unroll
        for (int mi = 0; mi < 2; ++mi)
#pragma unroll
            for (int ni = 0; ni < 4; ++ni)
#pragma unroll
                for (int r = 0; r < 4; ++r) acc[mi][ni][r] = 0.f;

        uint32_t bb = smem_base + GA_B_OFF;
#pragma unroll
        for (int ks = 0; ks < 12; ++ks) {
            uint32_t a[2][4];
#pragma unroll
            for (int mi = 0; mi < 2; ++mi) {
                uint32_t addr = smem_base + (wm * 32 + mi * 16 + lrow) * GA_RB + ks * 32 + lkh * 2;
                ldsm_x4(a[mi][0], a[mi][1], a[mi][2], a[mi][3], addr);
            }
            uint32_t bf[4][2];
#pragma unroll
            for (int nq = 0; nq < 2; ++nq) {
                uint32_t r0, r1, r2, r3;
                uint32_t addr = bb + (wn * 32 + nq * 16 + lrow) * GA_RB + ks * 32 + lkh * 2;
                ldsm_x4(r0, r1, r2, r3, addr);
                bf[2 * nq][0] = r0;     bf[2 * nq][1] = r2;
                bf[2 * nq + 1][0] = r1; bf[2 * nq + 1][1] = r3;
            }
#pragma unroll
            for (int mi = 0; mi < 2; ++mi)
#pragma unroll
                for (int ni = 0; ni < 4; ++ni)
                    mma_bf16(acc[mi][ni], a[mi], bf[ni]);
        }

#pragma unroll
        for (int mi = 0; mi < 2; ++mi) {
            int m = wm * 32 + mi * 16 + g;
            float* rowp = g_t + ((size_t)b * 256 + m) * NPIX + t * 64 + wn * 32 + T * 2;
#pragma unroll
            for (int ni = 0; ni < 4; ++ni) {
                *(u64*)(rowp + ni * 8) = pack2(acc[mi][ni][0], acc[mi][ni][1]);
                *(u64*)(rowp + ni * 8 + (size_t)8 * NPIX) = pack2(acc[mi][ni][2], acc[mi][ni][3]);
            }
        }
        t = nt;
        si = si + 1; if (si >= 3) si = 0;
    }
}

// ---------------- depthwise 3x3 conv + gate, float4 (round-9 exact) ----------
__global__ __launch_bounds__(256) void conv_mul(const float* __restrict__ w_dw)
{
    __shared__ float st[34][264];
    const int tid = threadIdx.x;
    const int jj = blockIdx.y, b = blockIdx.z, r0 = blockIdx.x * 32;

    const float* t1 = g_t + ((size_t)b * 256 + jj) * NPIX;
    const float* t2 = g_t + ((size_t)b * 256 + 128 + jj) * NPIX;
    float* outp = g_qv + ((size_t)b * 128 + jj) * NPIX;

    float wd[9];
#pragma unroll
    for (int i = 0; i < 9; ++i) wd[i] = w_dw[jj * 9 + i];

#pragma unroll
    for (int e = 0; e < 2176; e += 256) {
        int u = e + tid;
        if (u < 2176) {
            int rr = u >> 6, q4 = u & 63;
            int row = r0 - 1 + rr;
            float4 v = make_float4(0.f, 0.f, 0.f, 0.f);
            if (row >= 0 && row < 256)
                v = *(const float4*)(t1 + row * 256 + q4 * 4);
            *(float4*)&st[rr][4 + q4 * 4] = v;
        }
    }
    if (tid < 34) { st[tid][3] = 0.f; st[tid][260] = 0.f; }
    __syncthreads();

    const int ty = tid >> 6, tc = tid & 63;
    const int c0 = tc * 4;
#pragma unroll
    for (int r = ty * 8; r < ty * 8 + 8; ++r) {
        float s0 = 0.f, s1 = 0.f, s2 = 0.f, s3 = 0.f;
#pragma unroll
        for (int ky = 0; ky < 3; ++ky) {
            const float* rowp = &st[r + ky][4 + c0];
            float4 m = *(const float4*)rowp;
            float left = rowp[-1], right = rowp[4];
            float w0 = wd[ky * 3 + 0], w1 = wd[ky * 3 + 1], w2 = wd[ky * 3 + 2];
            s0 += w0 * left + w1 * m.x + w2 * m.y;
            s1 += w0 * m.x  + w1 * m.y + w2 * m.z;
            s2 += w0 * m.y  + w1 * m.z + w2 * m.w;
            s3 += w0 * m.z  + w1 * m.w + w2 * right;
        }
        int p = (r0 + r) * 256 + c0;
        float4 g4 = *(const float4*)(t2 + p);
        float4 o = make_float4(s0 * g4.x, s1 * g4.y, s2 * g4.z, s3 * g4.w);
        *(float4*)(outp + p) = o;
    }
}

// ---------------- tensor-core gram + sumsq (K-split warps) --------------------
#define GR_RB     208
#define GR_XRB    144
#define GR_A_OFF  0
#define GR_B_OFF  13312
#define GR_Q_OFF  26624
#define GR_V_OFF  35840
#define GR_STAGE  45056
#define GR_SMEM   (2 * GR_STAGE)
#define GR_NCHUNK 2048
__global__ __launch_bounds__(256, 2) void gram_mma()
{
    extern __shared__ char sm[];
    const int tid = threadIdx.x, wid = tid >> 5, lane = tid & 31;
    const int b = blockIdx.y;
    const int wk = wid >> 2;               // k-half
    const int warpM = wid & 1, warpN = (wid >> 1) & 1;

    const uint32_t smem_base = smem_to_u32(sm);
    const float* qsrc = g_qv + (size_t)b * 128 * NPIX;
    const float* vsrc = qsrc + (size_t)64 * NPIX;

    auto prefetch = [&](int ci, int s) {
        int pbase = ci * 32;
        uint32_t qb = smem_base + s * GR_STAGE + GR_Q_OFF;
        uint32_t vb = smem_base + s * GR_STAGE + GR_V_OFF;
#pragma unroll
        for (int e = 0; e < 512; e += 256) {
            int u = e + tid;
            int ch = u >> 3, sl = u & 7;
            cp16(qb + ch * GR_XRB + sl * 16, qsrc + (size_t)ch * NPIX + pbase + sl * 4);
        }
#pragma unroll
        for (int e = 0; e < 512; e += 256) {
            int u = e + tid;
            int ch = u >> 3, sl = u & 7;
            cp16(vb + ch * GR_XRB + sl * 16, vsrc + (size_t)ch * NPIX + pbase + sl * 4);
        }
    };

    const int lrow = lane & 15;
    const int lkh  = (lane >> 4) * 8;

    float acc[2][4][4];
#pragma unroll
    for (int mi = 0; mi < 2; ++mi)
#pragma unroll
        for (int ni = 0; ni < 4; ++ni)
#pragma unroll
            for (int r = 0; r < 4; ++r) acc[mi][ni][r] = 0.f;
    float ssq = 0.f, ssv = 0.f;

    const int cch = tid >> 2;
    const int ppr = (tid & 3) * 4;

    int ci = blockIdx.x;
    int s = 0;
    prefetch(ci, 0);
    CP_COMMIT();

    while (ci < GR_NCHUNK) {
        const int nci = ci + gridDim.x;
        const bool more = nci < GR_NCHUNK;
        if (more) { prefetch(nci, s ^ 1); CP_COMMIT(); CP_WAIT(1); }
        else      { CP_WAIT(0); }
        __syncthreads();

        {
            const float* rq = (const float*)(sm + s * GR_STAGE + GR_Q_OFF) + cch * 36 + ppr * 2;
            const float* rv = (const float*)(sm + s * GR_STAGE + GR_V_OFF) + cch * 36 + ppr * 2;
            float4 qa = *(const float4*)rq, qb4 = *(const float4*)(rq + 4);
            float4 va = *(const float4*)rv, vb4 = *(const float4*)(rv + 4);
            float qq[8] = {qa.x, qa.y, qa.z, qa.w, qb4.x, qb4.y, qb4.z, qb4.w};
            float vv[8] = {va.x, va.y, va.z, va.w, vb4.x, vb4.y, vb4.z, vb4.w};
            uint32_t wq[12], wv[12];
#pragma unroll
            for (int pr = 0; pr < 4; ++pr) {
                float q0 = qq[2 * pr], q1 = qq[2 * pr + 1];
                float v0 = vv[2 * pr], v1 = vv[2 * pr + 1];
                ssq += q0 * q0 + q1 * q1;
                ssv += v0 * v0 + v1 * v1;
                float qh0 = __bfloat162float(__float2bfloat16(q0));
                float qh1 = __bfloat162float(__float2bfloat16(q1));
                float vh0 = __bfloat162float(__float2bfloat16(v0));
                float vh1 = __bfloat162float(__float2bfloat16(v1));
                float ql0 = q0 - qh0, ql1 = q1 - qh1;
                float vl0 = v0 - vh0, vl1 = v1 - vh1;
                wq[pr * 3 + 0] = bfpair(qh0, qh0);
                wq[pr * 3 + 1] = bfpair(ql0, qh1);
                wq[pr * 3 + 2] = bfpair(qh1, ql1);
                wv[pr * 3 + 0] = bfpair(vh0, vl0);
                wv[pr * 3 + 1] = bfpair(vh0, vh1);
                wv[pr * 3 + 2] = bfpair(vl1, vh1);
            }
            uint32_t* aq = (uint32_t*)(sm + s * GR_STAGE + GR_A_OFF + cch * GR_RB) + ppr * 3;
            uint32_t* bv = (uint32_t*)(sm + s * GR_STAGE + GR_B_OFF + cch * GR_RB) + ppr * 3;
#pragma unroll
            for (int i = 0; i < 3; ++i) {
                *(uint4*)(aq + i * 4) = make_uint4(wq[i*4], wq[i*4+1], wq[i*4+2], wq[i*4+3]);
                *(uint4*)(bv + i * 4) = make_uint4(wv[i*4], wv[i*4+1], wv[i*4+2], wv[i*4+3]);
            }
        }
        __syncthreads();

        uint32_t ab = smem_base + s * GR_STAGE + GR_A_OFF;
        uint32_t bb = smem_base + s * GR_STAGE + GR_B_OFF;
#pragma unroll
        for (int ks3 = 0; ks3 < 3; ++ks3) {
            const int ks = wk * 3 + ks3;
            uint32_t a[2][4];
#pragma unroll
            for (int mi = 0; mi < 2; ++mi) {
                uint32_t addr = ab + (warpM * 32 + mi * 16 + lrow) * GR_RB + ks * 32 + lkh * 2;
                ldsm_x4(a[mi][0], a[mi][1], a[mi][2], a[mi][3], addr);
            }
            uint32_t bf[4][2];
#pragma unroll
            for (int nq = 0; nq < 2; ++nq) {
                uint32_t r0, r1, r2, r3;
                uint32_t addr = bb + (warpN * 32 + nq * 16 + lrow) * GR_RB + ks * 32 + lkh * 2;
                ldsm_x4(r0, r1, r2, r3, addr);
                bf[2 * nq][0] = r0;     bf[2 * nq][1] = r2;
                bf[2 * nq + 1][0] = r1; bf[2 * nq + 1][1] = r3;
            }
#pragma unroll
            for (int mi = 0; mi < 2; ++mi)
#pragma unroll
                for (int ni = 0; ni < 4; ++ni)
                    mma_bf16(acc[mi][ni], a[mi], bf[ni]);
        }
        __syncthreads();
        ci = nci;
        s ^= 1;
    }

    atomicAdd(&g_sumsq[b * 128 + cch], ssq);
    atomicAdd(&g_sumsq[b * 128 + 64 + cch], ssv);

    __syncthreads();
    float* red = (float*)sm + (warpM * 2 + warpN) * 1024;
    if (wk == 1) {
#pragma unroll
        for (int mi = 0; mi < 2; ++mi)
#pragma unroll
            for (int ni = 0; ni < 4; ++ni)
#pragma unroll
                for (int r = 0; r < 4; ++r)
                    red[(mi * 16 + ni * 4 + r) * 32 + lane] = acc[mi][ni][r];
    }
    __syncthreads();
    if (wk == 0) {
        const int g = lane >> 2, T = lane & 3;
        float* Gb = g_gram + b * 4096;
#pragma unroll
        for (int mi = 0; mi < 2; ++mi)
#pragma unroll
            for (int ni = 0; ni < 4; ++ni) {
                float r0 = acc[mi][ni][0] + red[(mi * 16 + ni * 4 + 0) * 32 + lane];
                float r1 = acc[mi][ni][1] + red[(mi * 16 + ni * 4 + 1) * 32 + lane];
                float r2 = acc[mi][ni][2] + red[(mi * 16 + ni * 4 + 2) * 32 + lane];
                float r3 = acc[mi][ni][3] + red[(mi * 16 + ni * 4 + 3) * 32 + lane];
                int m = warpM * 32 + mi * 16 + g;
                int n = warpN * 32 + ni * 8 + T * 2;
                atomicAdd(&Gb[m * 64 + n],           r0);
                atomicAdd(&Gb[m * 64 + n + 1],       r1);
                atomicAdd(&Gb[(m + 8) * 64 + n],     r2);
                atomicAdd(&Gb[(m + 8) * 64 + n + 1], r3);
            }
    }
}

// ---------------- norms + softmax + M = w_out @ attn (writes split M) --------
__global__ __launch_bounds__(256) void attn_kernel(
    const float* __restrict__ w_out, const float* __restrict__ temp_p)
{
    __shared__ float attn_s[64 * 65];
    __shared__ float wo_s[64 * 65];
    __shared__ float nrm[128];
    const int tid = threadIdx.x, b = blockIdx.x;

    if (tid < 128) nrm[tid] = fmaxf(sqrtf(g_sumsq[b * 128 + tid]), 1e-12f);
    for (int e = tid; e < 4096; e += 256) {
        int o = e >> 6, c = e & 63;
        wo_s[c * 65 + o] = w_out[e];
    }
    __syncthreads();

    const float temp = *temp_p;
    if (tid < 64) {
        int c = tid;
        float inq = temp / nrm[c];
        float mx = -1e30f;
        for (int d = 0; d < 64; ++d) {
            float l = g_gram[b * 4096 + c * 64 + d] * (inq / nrm[64 + d]);
            attn_s[c * 65 + d] = l;
            mx = fmaxf(mx, l);
        }
        float sum = 0.f;
        for (int d = 0; d < 64; ++d) {
            float e_ = expf(attn_s[c * 65 + d] - mx);
            attn_s[c * 65 + d] = e_;
            sum += e_;
        }
        float inv = 1.f / sum;
        for (int d = 0; d < 64; ++d) attn_s[c * 65 + d] *= inv;
    }
    __syncthreads();

    const int o = tid & 63, dg = tid >> 6;
    for (int d = dg * 16; d < dg * 16 + 16; ++d) {
        float m = 0.f;
#pragma unroll 8
        for (int c2 = 0; c2 < 64; ++c2) m += wo_s[c2 * 65 + o] * attn_s[c2 * 65 + d];
        __nv_bfloat16 hi = __float2bfloat16(m);
        __nv_bfloat16 lo = __float2bfloat16(m - __bfloat162float(hi));
        __nv_bfloat16* dst = g_M2 + ((size_t)b * 64 + o) * 192 + 3 * d;
        dst[0] = hi; dst[1] = hi; dst[2] = lo;
    }
}

// ---------------- tensor-core gemm2: out = M @ v (round-13 exact) ------------
#define G2_A_RB   400
#define G2_A_ARR  (64 * G2_A_RB)
#define G2_B_RB   112
#define G2_B_ARR  (128 * G2_B_RB)
#define G2_X_RB   528
#define G2_X_ARR  (16 * G2_X_RB)
#define G2_STAGE  (G2_B_ARR + G2_X_ARR)
#define G2_SMEM   (G2_A_ARR + 2 * G2_STAGE)
__global__ __launch_bounds__(256, 2) void gemm2_mma(float* __restrict__ out)
{
    extern __shared__ char sm[];
    const int tid = threadIdx.x, wid = tid >> 5, lane = tid & 31;
    const int pbase = blockIdx.x * 128;
    const int b = blockIdx.y;
    const int warpM = wid & 1, warpN = wid >> 1;

    const uint32_t smem_base = smem_to_u32(sm);
    const char*  Agl = (const char*)(g_M2 + (size_t)b * 64 * 192);
    const float* vb  = g_qv + (size_t)b * 128 * NPIX + (size_t)64 * NPIX + pbase;

    auto b_base = [&](int s) { return smem_base + G2_A_ARR + s * G2_STAGE; };
    auto x_base = [&](int s) { return smem_base + G2_A_ARR + s * G2_STAGE + G2_B_ARR; };

#pragma unroll
    for (int e = 0; e < 1536; e += 256) {
        int u = e + tid;
        int r = u / 24, sl = u % 24;
        cp16(smem_base + r * G2_A_RB + sl * 16, Agl + r * 384 + sl * 16);
    }
    auto prefetch = [&](int chunk, int s) {
        uint32_t xbs = x_base(s);
#pragma unroll
        for (int e = 0; e < 512; e += 256) {
            int u = e + tid;
            int ch = u >> 5, sl = u & 31;
            cp16(xbs + ch * G2_X_RB + sl * 16,
                 vb + (size_t)(chunk * 16 + ch) * NPIX + sl * 4);
        }
    };
    prefetch(0, 0);
    CP_COMMIT();

    const int lrow = lane & 15;
    const int lkh  = (lane >> 4) * 8;
    const int cv_p = tid & 127;
    const int cv_g = tid >> 7;

    float acc[2][4][4];
#pragma unroll
    for (int mi = 0; mi < 2; ++mi)
#pragma unroll
        for (int ni = 0; ni < 4; ++ni)
#pragma unroll
            for (int r = 0; r < 4; ++r) acc[mi][ni][r] = 0.f;

#pragma unroll
    for (int c = 0; c < 4; ++c) {
        const int s = c & 1;
        if (c < 3) { prefetch(c + 1, s ^ 1); CP_COMMIT(); }
        if (c < 3) CP_WAIT(1); else CP_WAIT(0);
        __syncthreads();

        {
            const float* xs = (const float*)(sm + G2_A_ARR + s * G2_STAGE + G2_B_ARR);
            char* Bs = sm + G2_A_ARR + s * G2_STAGE;
            uint32_t w[12];
#pragma unroll
            for (int i = 0; i < 4; ++i) {
                int cpi = cv_g * 4 + i;
                float x0 = xs[(2 * cpi) * 132 + cv_p];
                float x1 = xs[(2 * cpi + 1) * 132 + cv_p];
                float h0 = __bfloat162float(__float2bfloat16(x0));
                float h1 = __bfloat162float(__float2bfloat16(x1));
                float l0 = x0 - h0, l1 = x1 - h1;
                w[i * 3 + 0] = bfpair(h0, l0);
                w[i * 3 + 1] = bfpair(h0, h1);
                w[i * 3 + 2] = bfpair(l1, h1);
            }
            uint32_t* brow = (uint32_t*)(Bs + cv_p * G2_B_RB) + cv_g * 12;
#pragma unroll
            for (int i = 0; i < 3; ++i)
                *(uint4*)(brow + i * 4) = make_uint4(w[i*4], w[i*4+1], w[i*4+2], w[i*4+3]);
        }
        __syncthreads();

        uint32_t bb = b_base(s);
#pragma unroll
        for (int ksl = 0; ksl < 3; ++ksl) {
            uint32_t a[2][4];
#pragma unroll
            for (int mi = 0; mi < 2; ++mi) {
                uint32_t addr = smem_base + (warpM * 32 + mi * 16 + lrow) * G2_A_RB
                              + c * 96 + ksl * 32 + lkh * 2;
                ldsm_x4(a[mi][0], a[mi][1], a[mi][2], a[mi][3], addr);
            }
            uint32_t bf[4][2];
#pragma unroll
            for (int nq = 0; nq < 2; ++nq) {
                uint32_t r0, r1, r2, r3;
                uint32_t addr = bb + (warpN * 32 + nq * 16 + lrow) * G2_B_RB + ksl * 32 + lkh * 2;
                ldsm_x4(r0, r1, r2, r3, addr);
                bf[2 * nq][0] = r0;     bf[2 * nq][1] = r2;
                bf[2 * nq + 1][0] = r1; bf[2 * nq + 1][1] = r3;
            }
#pragma unroll
            for (int mi = 0; mi < 2; ++mi)
#pragma unroll
                for (int ni = 0; ni < 4; ++ni)
                    mma_bf16(acc[mi][ni], a[mi], bf[ni]);
        }
        __syncthreads();
    }

    const int g = lane >> 2, T = lane & 3;
#pragma unroll
    for (int mi = 0; mi < 2; ++mi) {
        int o = warpM * 32 + mi * 16 + g;
        float* rowp = out + ((size_t)b * 64 + o) * NPIX + pbase + warpN * 32 + T * 2;
#pragma unroll
        for (int ni = 0; ni < 4; ++ni) {
            *(u64*)(rowp + ni * 8) = pack2(acc[mi][ni][0], acc[mi][ni][1]);
            *(u64*)(rowp + ni * 8 + (size_t)8 * NPIX) = pack2(acc[mi][ni][2], acc[mi][ni][3]);
        }
    }
}

// ---------------- launch ------------------------------------------------------
extern "C" void kernel_launch(void* const* d_in, const int* in_sizes, int n_in,
                              void* d_out, int out_size)
{
    const float* x      = (const float*)d_in[0];
    const float* w_in   = (const float*)d_in[1];
    const float* w_dw   = (const float*)d_in[2];
    const float* w_out  = (const float*)d_in[3];
    const float* temp   = (const float*)d_in[4];
    float* out = (float*)d_out;

    cudaFuncSetAttribute(gemm1_res, cudaFuncAttributeMaxDynamicSharedMemorySize, GA_SMEM);
    cudaFuncSetAttribute(gram_mma,  cudaFuncAttributeMaxDynamicSharedMemorySize, GR_SMEM);
    cudaFuncSetAttribute(gemm2_mma, cudaFuncAttributeMaxDynamicSharedMemorySize, G2_SMEM);

    // weight split + stat zeroing (merged)
    wsplit<<<64, 256>>>(w_in);

    // t = w_in @ x  (tensor cores, A-resident, 3-stage X ring)
    gemm1_res<<<dim3(GA_GRIDX, 1, BATCH), 512, GA_SMEM>>>(x);

    // depthwise conv + gate -> qv (float4)
    conv_mul<<<dim3(8, 128, BATCH), 256>>>(w_dw);

    // gram + sumsq (tensor cores, K-split warps)
    gram_mma<<<dim3(148, BATCH), 256, GR_SMEM>>>();

    // norms, softmax, M = w_out @ attn (+ bf16-split M)
    attn_kernel<<<BATCH, 256>>>(w_out, temp);

    // out = M @ v (tensor cores, fused split)
    gemm2_mma<<<dim3(NPIX / 128, BATCH), 256, G2_SMEM>>>(out);
}